// round 14
// baseline (speedup 1.0000x reference)
#include <cuda_runtime.h>
#include <cuda_fp16.h>
#include <mma.h>
#include <math.h>
#include <stdint.h>

using namespace nvcuda;

#define NB  16
#define SEQ 1024
#define DIM 1024
#define OFF2 ((size_t)NB * SEQ * 2048)

// ---------------------------------------------------------------------------
// Scratch (__device__ globals; allocation-free rule)
// ---------------------------------------------------------------------------
__device__ __align__(256) __half g_aH[(size_t)NB * SEQ * DIM];  // fp16(lhs * w_prod)
__device__ __align__(256) __half g_lH[(size_t)NB * SEQ * DIM];  // fp16(lhs)
__device__ __align__(256) __half g_rH[(size_t)NB * SEQ * DIM];  // fp16(rhs)
__device__ __align__(256) __half g_E [(size_t)NB * SEQ * SEQ];  // exp(tanh(score)) [b][l][r]
__device__ float g_u[NB * SEQ];
__device__ float g_v[NB * SEQ];
__device__ float g_rinv[NB * SEQ];
__device__ float g_cinv[NB * SEQ];
__device__ float g_rpart[8 * NB * SEQ];     // rowsum partials per j-tile
__device__ float g_cpart[NB * 8 * SEQ];     // colsum partials per l-chunk

// ---------------------------------------------------------------------------
// PTX helpers (compute_103-safe)
// ---------------------------------------------------------------------------
__device__ __forceinline__ uint32_t smem_u32(const void* p) {
  uint32_t a;
  asm("{ .reg .u64 t; cvta.to.shared.u64 t, %1; cvt.u32.u64 %0, t; }"
      : "=r"(a) : "l"(p));
  return a;
}
__device__ __forceinline__ void cp_async16(uint32_t dst, const void* src) {
  asm volatile("cp.async.cg.shared.global [%0], [%1], 16;"
               :: "r"(dst), "l"(src) : "memory");
}
template <int N> __device__ __forceinline__ void cp_wait() {
  asm volatile("cp.async.wait_group %0;" :: "n"(N) : "memory");
}
__device__ __forceinline__ void cp_commit() {
  asm volatile("cp.async.commit_group;" ::: "memory");
}

// ---------------------------------------------------------------------------
// fuse: single pass produces fp16 operands, identity output halves, u, v
// ---------------------------------------------------------------------------
__global__ __launch_bounds__(256) void fuse_kernel(
    const float4* __restrict__ lhs, const float4* __restrict__ rhs,
    const float4* __restrict__ w, float4* __restrict__ out) {
  const int row = blockIdx.x;
  const int t = threadIdx.x;
  const size_t i = (size_t)row * 256 + t;

  float4 x = lhs[i];
  float4 y = rhs[i];
  float4 wp = w[t];
  float4 wl = w[256 + t];
  float4 wr = w[512 + t];

  out[(size_t)row * 512 + t] = x;
  out[OFF2 / 4 + (size_t)row * 512 + t] = y;

  __half2* aH2 = (__half2*)g_aH;
  __half2* lH2 = (__half2*)g_lH;
  __half2* rH2 = (__half2*)g_rH;
  aH2[2 * i]     = __floats2half2_rn(x.x * wp.x, x.y * wp.y);
  aH2[2 * i + 1] = __floats2half2_rn(x.z * wp.z, x.w * wp.w);
  lH2[2 * i]     = __floats2half2_rn(x.x, x.y);
  lH2[2 * i + 1] = __floats2half2_rn(x.z, x.w);
  rH2[2 * i]     = __floats2half2_rn(y.x, y.y);
  rH2[2 * i + 1] = __floats2half2_rn(y.z, y.w);

  __shared__ float red[512];
  red[t]       = x.x * wl.x + x.y * wl.y + x.z * wl.z + x.w * wl.w;
  red[256 + t] = y.x * wr.x + y.y * wr.y + y.z * wr.z + y.w * wr.w;
  __syncthreads();
  for (int o = 128; o > 0; o >>= 1) {
    if (t < o) {
      red[t] += red[t + o];
      red[256 + t] += red[256 + t + o];
    }
    __syncthreads();
  }
  if (t == 0) {
    g_u[row] = red[0];
    g_v[row] = red[256];
  }
}

// ---------------------------------------------------------------------------
// GEMM body: CTA tile 256(m) x 128(n), K=1024, 8 warps of 64x64.
//   MODE 0: C[l][r] = aH . rH^T      (A NK row, B NK col)  -> E + rowsum part
//   MODE 1: C[l][d] = E . rH         (A NK row, B KN row)  -> out * rinv
//   MODE 2: C[r][d] = E^T . lH       (A KN col, B KN row)  -> out * cinv
// SMEM per stage: A-sect 36864 (NK 256x72h / KN 64x264h), B-sect 18432.
// 3 stages = 165888 B. Epilogue staged in two 128-row passes through 64KB.
// ---------------------------------------------------------------------------
#define ASECT  36864
#define STAGEB (ASECT + 18432)           // 55296
#define GSMEM  (3 * STAGEB)              // 165888

template <int MODE>
__device__ __forceinline__ void gemm_body(int b, const float* bias, float* out,
                                          char* smem) {
  const uint32_t sb = smem_u32(smem);
  const int tid = threadIdx.x, wid = tid >> 5;
  const int i0 = blockIdx.y * 256, j0 = blockIdx.x * 128;
  const int wmw = (wid & 3) * 64;   // warp m offset (4 warps in m)
  const int wn  = (wid >> 2) * 64;  // warp n offset (2 warps in n)

  constexpr bool A_NK = (MODE <= 1);

  const __half* Asrc =
      (MODE == 0) ? g_aH + ((size_t)b * SEQ + i0) * 1024
    : (MODE == 1) ? g_E  + ((size_t)b * SEQ + i0) * 1024
                  : g_E  + (size_t)b * SEQ * SEQ;            // KN, cols i0
  const __half* Bsrc =
      (MODE == 0) ? g_rH + ((size_t)b * SEQ + j0) * 1024
                  : ((MODE == 1) ? g_rH : g_lH) + (size_t)b * SEQ * 1024;

  wmma::fragment<wmma::accumulator, 16, 16, 16, float> c[4][4];
#pragma unroll
  for (int mt = 0; mt < 4; mt++)
#pragma unroll
    for (int nt = 0; nt < 4; nt++) wmma::fill_fragment(c[mt][nt], 0.0f);

#define ISSUE(k0, s)                                                          \
  do {                                                                        \
    uint32_t ab_ = sb + (s) * STAGEB;                                         \
    uint32_t bb_ = ab_ + ASECT;                                               \
    _Pragma("unroll")                                                         \
    for (int q = 0; q < 8; q++) {         /* A: 2048 16B chunks */            \
      int idx_ = q * 256 + tid;                                               \
      if (A_NK) {                                                             \
        int row_ = idx_ >> 3, c_ = idx_ & 7;                                  \
        cp_async16(ab_ + row_ * 144 + c_ * 16,                                \
                   Asrc + (size_t)row_ * 1024 + (k0) + c_ * 8);               \
      } else {                                                                \
        int row_ = idx_ >> 5, c_ = idx_ & 31;                                 \
        cp_async16(ab_ + row_ * 528 + c_ * 16,                                \
                   Asrc + (size_t)((k0) + row_) * 1024 + i0 + c_ * 8);        \
      }                                                                       \
    }                                                                         \
    _Pragma("unroll")                                                         \
    for (int q = 0; q < 4; q++) {         /* B: 1024 16B chunks */            \
      int idx_ = q * 256 + tid;                                               \
      if (MODE == 0) {                                                        \
        int row_ = idx_ >> 3, c_ = idx_ & 7;                                  \
        cp_async16(bb_ + row_ * 144 + c_ * 16,                                \
                   Bsrc + (size_t)row_ * 1024 + (k0) + c_ * 8);               \
      } else {                                                                \
        int row_ = idx_ >> 4, c_ = idx_ & 15;                                 \
        cp_async16(bb_ + row_ * 272 + c_ * 16,                                \
                   Bsrc + (size_t)((k0) + row_) * 1024 + j0 + c_ * 8);        \
      }                                                                       \
    }                                                                         \
    cp_commit();                                                              \
  } while (0)

  ISSUE(0, 0);
  ISSUE(64, 1);
#pragma unroll 1
  for (int ch = 0; ch < 16; ++ch) {
    cp_wait<1>();
    __syncthreads();
    if (ch + 2 < 16) ISSUE((ch + 2) * 64, (ch + 2) % 3);
    else             cp_commit();

    const int buf = ch % 3;
    const __half* As = (const __half*)(smem + buf * STAGEB);
    const __half* Bs = (const __half*)(smem + buf * STAGEB + ASECT);
#pragma unroll
    for (int ks = 0; ks < 4; ++ks) {
      const int kk = ks * 16;
      if constexpr (A_NK) {
        wmma::fragment<wmma::matrix_a, 16, 16, 16, __half, wmma::row_major> af[4];
#pragma unroll
        for (int mt = 0; mt < 4; mt++)
          wmma::load_matrix_sync(af[mt], As + (wmw + mt * 16) * 72 + kk, 72);
#pragma unroll
        for (int nt = 0; nt < 4; nt++) {
          if constexpr (MODE == 0) {
            wmma::fragment<wmma::matrix_b, 16, 16, 16, __half, wmma::col_major> bf;
            wmma::load_matrix_sync(bf, Bs + (wn + nt * 16) * 72 + kk, 72);
#pragma unroll
            for (int mt = 0; mt < 4; mt++)
              wmma::mma_sync(c[mt][nt], af[mt], bf, c[mt][nt]);
          } else {
            wmma::fragment<wmma::matrix_b, 16, 16, 16, __half, wmma::row_major> bf;
            wmma::load_matrix_sync(bf, Bs + kk * 136 + wn + nt * 16, 136);
#pragma unroll
            for (int mt = 0; mt < 4; mt++)
              wmma::mma_sync(c[mt][nt], af[mt], bf, c[mt][nt]);
          }
        }
      } else {
        wmma::fragment<wmma::matrix_a, 16, 16, 16, __half, wmma::col_major> af[4];
#pragma unroll
        for (int mt = 0; mt < 4; mt++)
          wmma::load_matrix_sync(af[mt], As + kk * 264 + wmw + mt * 16, 264);
#pragma unroll
        for (int nt = 0; nt < 4; nt++) {
          wmma::fragment<wmma::matrix_b, 16, 16, 16, __half, wmma::row_major> bf;
          wmma::load_matrix_sync(bf, Bs + kk * 136 + wn + nt * 16, 136);
#pragma unroll
          for (int mt = 0; mt < 4; mt++)
            wmma::mma_sync(c[mt][nt], af[mt], bf, c[mt][nt]);
        }
      }
    }
  }
#undef ISSUE
  __syncthreads();

  // ---- epilogue: two 128-row passes through a 128x128 f32 buffer
  float* sf = (float*)smem;
#pragma unroll 1
  for (int p = 0; p < 2; ++p) {
#pragma unroll
    for (int mt = 0; mt < 2; mt++)
#pragma unroll
      for (int nt = 0; nt < 4; nt++)
        wmma::store_matrix_sync(
            sf + (size_t)((wid & 3) * 32 + mt * 16) * 128 + wn + nt * 16,
            c[2 * p + mt][nt], 128, wmma::mem_row_major);
    __syncthreads();

    const int r = tid >> 1;                 // buffer row 0..127
    const int chalf = (tid & 1) * 64;
    const int gi = i0 + (r >> 5) * 64 + p * 32 + (r & 31);  // global m row
    const float* srow = sf + (size_t)r * 128 + chalf;

    if (MODE == 0) {
      const float u0 = g_u[b * SEQ + gi] + bias[0];
      __half* erow = g_E + ((size_t)b * SEQ + gi) * 1024 + j0 + chalf;
      float rsum = 0.f;
#pragma unroll
      for (int q = 0; q < 16; ++q) {
        float4 s4 = *(const float4*)(srow + q * 4);
        const int col = j0 + chalf + q * 4;
        float e0 = __expf(tanhf(s4.x + u0 + g_v[b * SEQ + col]));
        float e1 = __expf(tanhf(s4.y + u0 + g_v[b * SEQ + col + 1]));
        float e2 = __expf(tanhf(s4.z + u0 + g_v[b * SEQ + col + 2]));
        float e3 = __expf(tanhf(s4.w + u0 + g_v[b * SEQ + col + 3]));
        rsum += (e0 + e1) + (e2 + e3);
        *(__half2*)(erow + q * 4)     = __floats2half2_rn(e0, e1);
        *(__half2*)(erow + q * 4 + 2) = __floats2half2_rn(e2, e3);
      }
      rsum += __shfl_xor_sync(0xffffffff, rsum, 1);
      if ((tid & 1) == 0)
        g_rpart[(size_t)blockIdx.x * (NB * SEQ) + b * SEQ + gi] = rsum;
    } else {
      const float iv = ((MODE == 1) ? g_rinv : g_cinv)[b * SEQ + gi];
      float4* orow =
          (float4*)(out + ((size_t)b * SEQ + gi) * 2048 + 1024 + j0 + chalf);
#pragma unroll
      for (int q = 0; q < 16; ++q) {
        float4 s4 = *(const float4*)(srow + q * 4);
        orow[q] = make_float4(s4.x * iv, s4.y * iv, s4.z * iv, s4.w * iv);
      }
    }
    __syncthreads();
  }
}

__global__ __launch_bounds__(256) void score_kernel(const float* __restrict__ bias,
                                                    float* __restrict__ out) {
  extern __shared__ char smem[];
  gemm_body<0>(blockIdx.z, bias, out, smem);
}

// merged av kernel: z<16 -> MODE1 (lhs attn), z>=16 -> MODE2 (rhs attn)
__global__ __launch_bounds__(256) void av_kernel(const float* __restrict__ bias,
                                                 float* __restrict__ out) {
  extern __shared__ char smem[];
  if (blockIdx.z < NB) gemm_body<1>(blockIdx.z, bias, out, smem);
  else                 gemm_body<2>(blockIdx.z - NB, bias, out + OFF2, smem);
}

// ---------------------------------------------------------------------------
// colsum(E) partials over 128-row chunks (coalesced in r)
// ---------------------------------------------------------------------------
__global__ void colsum_part() {
  const int b = blockIdx.z, chunk = blockIdx.y;
  const int r = blockIdx.x * 256 + threadIdx.x;
  const __half* e = g_E + (size_t)b * SEQ * SEQ + (size_t)chunk * 128 * SEQ + r;
  float s = 0.f;
#pragma unroll 8
  for (int l = 0; l < 128; l++) s += __half2float(e[(size_t)l * SEQ]);
  g_cpart[(b * 8 + chunk) * SEQ + r] = s;
}

// ---------------------------------------------------------------------------
// finalize: rinv from 8 row partials, cinv from 8 col partials
// ---------------------------------------------------------------------------
__global__ void finalize_kernel() {
  const int idx = blockIdx.x * 256 + threadIdx.x;
  const int b = idx >> 10;
  float sr = 0.f, sc = 0.f;
#pragma unroll
  for (int j = 0; j < 8; j++) sr += g_rpart[(size_t)j * (NB * SEQ) + idx];
#pragma unroll
  for (int c = 0; c < 8; c++) sc += g_cpart[(b * 8 + c) * SEQ + (idx & 1023)];
  g_rinv[idx] = 1.0f / sr;
  g_cinv[idx] = 1.0f / sc;
}

// ---------------------------------------------------------------------------
extern "C" void kernel_launch(void* const* d_in, const int* in_sizes, int n_in,
                              void* d_out, int out_size) {
  const float* lhs = (const float*)d_in[0];
  const float* rhs = (const float*)d_in[1];
  const float* w   = (const float*)d_in[2];
  const float* bp  = (const float*)d_in[3];
  float* out = (float*)d_out;

  cudaFuncSetAttribute(score_kernel, cudaFuncAttributeMaxDynamicSharedMemorySize, GSMEM);
  cudaFuncSetAttribute(av_kernel,    cudaFuncAttributeMaxDynamicSharedMemorySize, GSMEM);

  fuse_kernel<<<NB * SEQ, 256>>>((const float4*)lhs, (const float4*)rhs,
                                 (const float4*)w, (float4*)out);

  score_kernel<<<dim3(8, 4, NB), 256, GSMEM>>>(bp, out);   // -> g_E + rpart
  colsum_part<<<dim3(4, 8, NB), 256>>>();
  finalize_kernel<<<NB * SEQ / 256, 256>>>();              // rinv + cinv

  av_kernel<<<dim3(8, 4, 2 * NB), 256, GSMEM>>>(bp, out);  // both attn outputs
}

// round 15
// speedup vs baseline: 4.2744x; 4.2744x over previous
#include <cuda_runtime.h>
#include <cuda_fp16.h>
#include <mma.h>
#include <math.h>
#include <stdint.h>

using namespace nvcuda;

#define NB  16
#define SEQ 1024
#define DIM 1024
#define OFF2 ((size_t)NB * SEQ * 2048)

// ---------------------------------------------------------------------------
// Scratch (__device__ globals; allocation-free rule)
// ---------------------------------------------------------------------------
__device__ __align__(256) __half g_aH[(size_t)NB * SEQ * DIM];  // fp16(lhs * w_prod)
__device__ __align__(256) __half g_lH[(size_t)NB * SEQ * DIM];  // fp16(lhs)
__device__ __align__(256) __half g_rH[(size_t)NB * SEQ * DIM];  // fp16(rhs)
__device__ __align__(256) __half g_E [(size_t)NB * SEQ * SEQ];  // exp(tanh(score)) [b][l][r]
__device__ float g_u[NB * SEQ];
__device__ float g_v[NB * SEQ];
__device__ float g_rinv[NB * SEQ];
__device__ float g_cinv[NB * SEQ];
__device__ float g_rpart[8 * NB * SEQ];     // rowsum partials per j-tile
__device__ float g_cpart[NB * 8 * SEQ];     // colsum partials per l-chunk

// ---------------------------------------------------------------------------
// PTX helpers (compute_103-safe)
// ---------------------------------------------------------------------------
__device__ __forceinline__ uint32_t smem_u32(const void* p) {
  uint32_t a;
  asm("{ .reg .u64 t; cvta.to.shared.u64 t, %1; cvt.u32.u64 %0, t; }"
      : "=r"(a) : "l"(p));
  return a;
}
__device__ __forceinline__ void cp_async16(uint32_t dst, const void* src) {
  asm volatile("cp.async.cg.shared.global [%0], [%1], 16;"
               :: "r"(dst), "l"(src) : "memory");
}
template <int N> __device__ __forceinline__ void cp_wait() {
  asm volatile("cp.async.wait_group %0;" :: "n"(N) : "memory");
}
__device__ __forceinline__ void cp_commit() {
  asm volatile("cp.async.commit_group;" ::: "memory");
}

// ---------------------------------------------------------------------------
// fuse: single pass produces fp16 operands, identity output halves, u, v
// ---------------------------------------------------------------------------
__global__ __launch_bounds__(256) void fuse_kernel(
    const float4* __restrict__ lhs, const float4* __restrict__ rhs,
    const float4* __restrict__ w, float4* __restrict__ out) {
  const int row = blockIdx.x;
  const int t = threadIdx.x;
  const size_t i = (size_t)row * 256 + t;

  float4 x = lhs[i];
  float4 y = rhs[i];
  float4 wp = w[t];
  float4 wl = w[256 + t];
  float4 wr = w[512 + t];

  out[(size_t)row * 512 + t] = x;
  out[OFF2 / 4 + (size_t)row * 512 + t] = y;

  __half2* aH2 = (__half2*)g_aH;
  __half2* lH2 = (__half2*)g_lH;
  __half2* rH2 = (__half2*)g_rH;
  aH2[2 * i]     = __floats2half2_rn(x.x * wp.x, x.y * wp.y);
  aH2[2 * i + 1] = __floats2half2_rn(x.z * wp.z, x.w * wp.w);
  lH2[2 * i]     = __floats2half2_rn(x.x, x.y);
  lH2[2 * i + 1] = __floats2half2_rn(x.z, x.w);
  rH2[2 * i]     = __floats2half2_rn(y.x, y.y);
  rH2[2 * i + 1] = __floats2half2_rn(y.z, y.w);

  __shared__ float red[512];
  red[t]       = x.x * wl.x + x.y * wl.y + x.z * wl.z + x.w * wl.w;
  red[256 + t] = y.x * wr.x + y.y * wr.y + y.z * wr.z + y.w * wr.w;
  __syncthreads();
  for (int o = 128; o > 0; o >>= 1) {
    if (t < o) {
      red[t] += red[t + o];
      red[256 + t] += red[256 + t + o];
    }
    __syncthreads();
  }
  if (t == 0) {
    g_u[row] = red[0];
    g_v[row] = red[256];
  }
}

// ---------------------------------------------------------------------------
// GEMM body (exact round-9 shape: proven 465.7us / rel_err 1.03e-5):
// 128x128 CTA tile, 8 warps of 32x64, K=1024, 3-stage cp.async.
//   MODE 0: C[l][r] = aH . rH^T      (A NK row, B NK col)  -> E + rowsum part
//   MODE 1: C[l][d] = E . rH         (A NK row, B KN row)  -> out * rinv
//   MODE 2: C[r][d] = E^T . lH       (A KN col, B KN row)  -> out * cinv
// NK tile: 128 rows x 64 halves, stride 72. KN tile: 64 x 128, stride 136.
// ---------------------------------------------------------------------------
#define STAGEB  36864                    // A-sect 18432 + B-sect 18432
#define GSMEM   (3 * STAGEB)             // 110592; epilogue reuses 64KB

template <int MODE>
__device__ __forceinline__ void gemm_body(int b, const float* bias, float* out,
                                          char* smem) {
  const uint32_t sb = smem_u32(smem);
  const int tid = threadIdx.x, wid = tid >> 5;
  const int i0 = blockIdx.y * 128, j0 = blockIdx.x * 128;
  const int wm = (wid & 3) * 32;
  const int wn = (wid >> 2) * 64;

  constexpr bool A_NK = (MODE <= 1);
  constexpr bool B_NK = (MODE == 0);

  const __half* Asrc =
      (MODE == 0) ? g_aH + ((size_t)b * SEQ + i0) * 1024
    : (MODE == 1) ? g_E  + ((size_t)b * SEQ + i0) * 1024
                  : g_E  + (size_t)b * SEQ * SEQ;            // KN: cols i0
  const __half* Bsrc =
      (MODE == 0) ? g_rH + ((size_t)b * SEQ + j0) * 1024
                  : ((MODE == 1) ? g_rH : g_lH) + (size_t)b * SEQ * 1024;

  wmma::fragment<wmma::accumulator, 16, 16, 16, float> c[2][4];
#pragma unroll
  for (int mt = 0; mt < 2; mt++)
#pragma unroll
    for (int nt = 0; nt < 4; nt++) wmma::fill_fragment(c[mt][nt], 0.0f);

#define ISSUE(k0, s)                                                          \
  do {                                                                        \
    uint32_t ab_ = sb + (s) * STAGEB;                                         \
    uint32_t bb_ = ab_ + 18432;                                               \
    _Pragma("unroll")                                                         \
    for (int q = 0; q < 4; q++) {                                             \
      int idx_ = q * 256 + tid;                                               \
      if (A_NK) {                                                             \
        int row_ = idx_ >> 3, c_ = idx_ & 7;                                  \
        cp_async16(ab_ + row_ * 144 + c_ * 16,                                \
                   Asrc + (size_t)row_ * 1024 + (k0) + c_ * 8);               \
      } else {                                                                \
        int row_ = idx_ >> 4, c_ = idx_ & 15;                                 \
        cp_async16(ab_ + row_ * 272 + c_ * 16,                                \
                   Asrc + (size_t)((k0) + row_) * 1024 + i0 + c_ * 8);        \
      }                                                                       \
      if (B_NK) {                                                             \
        int row_ = idx_ >> 3, c_ = idx_ & 7;                                  \
        cp_async16(bb_ + row_ * 144 + c_ * 16,                                \
                   Bsrc + (size_t)row_ * 1024 + (k0) + c_ * 8);               \
      } else {                                                                \
        int row_ = idx_ >> 4, c_ = idx_ & 15;                                 \
        cp_async16(bb_ + row_ * 272 + c_ * 16,                                \
                   Bsrc + (size_t)((k0) + row_) * 1024 + j0 + c_ * 8);        \
      }                                                                       \
    }                                                                         \
    cp_commit();                                                              \
  } while (0)

  ISSUE(0, 0);
  ISSUE(64, 1);
#pragma unroll 1
  for (int ch = 0; ch < 16; ++ch) {
    cp_wait<1>();
    __syncthreads();
    if (ch + 2 < 16) ISSUE((ch + 2) * 64, (ch + 2) % 3);
    else             cp_commit();

    const int buf = ch % 3;
    const __half* As = (const __half*)(smem + buf * STAGEB);
    const __half* Bs = (const __half*)(smem + buf * STAGEB + 18432);
#pragma unroll
    for (int ks = 0; ks < 4; ++ks) {
      const int kk = ks * 16;
      if constexpr (A_NK && B_NK) {            // MODE 0
        wmma::fragment<wmma::matrix_a, 16, 16, 16, __half, wmma::row_major> af[2];
#pragma unroll
        for (int mt = 0; mt < 2; mt++)
          wmma::load_matrix_sync(af[mt], As + (wm + mt * 16) * 72 + kk, 72);
#pragma unroll
        for (int nt = 0; nt < 4; nt++) {
          wmma::fragment<wmma::matrix_b, 16, 16, 16, __half, wmma::col_major> bf;
          wmma::load_matrix_sync(bf, Bs + (wn + nt * 16) * 72 + kk, 72);
          wmma::mma_sync(c[0][nt], af[0], bf, c[0][nt]);
          wmma::mma_sync(c[1][nt], af[1], bf, c[1][nt]);
        }
      } else if constexpr (A_NK && !B_NK) {    // MODE 1
        wmma::fragment<wmma::matrix_a, 16, 16, 16, __half, wmma::row_major> af[2];
#pragma unroll
        for (int mt = 0; mt < 2; mt++)
          wmma::load_matrix_sync(af[mt], As + (wm + mt * 16) * 72 + kk, 72);
#pragma unroll
        for (int nt = 0; nt < 4; nt++) {
          wmma::fragment<wmma::matrix_b, 16, 16, 16, __half, wmma::row_major> bf;
          wmma::load_matrix_sync(bf, Bs + kk * 136 + wn + nt * 16, 136);
          wmma::mma_sync(c[0][nt], af[0], bf, c[0][nt]);
          wmma::mma_sync(c[1][nt], af[1], bf, c[1][nt]);
        }
      } else {                                 // MODE 2
        wmma::fragment<wmma::matrix_a, 16, 16, 16, __half, wmma::col_major> af[2];
#pragma unroll
        for (int mt = 0; mt < 2; mt++)
          wmma::load_matrix_sync(af[mt], As + kk * 136 + wm + mt * 16, 136);
#pragma unroll
        for (int nt = 0; nt < 4; nt++) {
          wmma::fragment<wmma::matrix_b, 16, 16, 16, __half, wmma::row_major> bf;
          wmma::load_matrix_sync(bf, Bs + kk * 136 + wn + nt * 16, 136);
          wmma::mma_sync(c[0][nt], af[0], bf, c[0][nt]);
          wmma::mma_sync(c[1][nt], af[1], bf, c[1][nt]);
        }
      }
    }
  }
#undef ISSUE
  __syncthreads();

  // ---- stage accumulators to SMEM (compiler-owned layout), plain epilogue
  float* sf = (float*)smem;                 // 128x128 f32 = 64KB
#pragma unroll
  for (int mt = 0; mt < 2; mt++)
#pragma unroll
    for (int nt = 0; nt < 4; nt++)
      wmma::store_matrix_sync(sf + (size_t)(wm + mt * 16) * 128 + wn + nt * 16,
                              c[mt][nt], 128, wmma::mem_row_major);
  __syncthreads();

  const int r = tid >> 1;                   // 0..127
  const int chalf = (tid & 1) * 64;
  const int ri = i0 + r;
  const float* srow = sf + (size_t)r * 128 + chalf;

  if (MODE == 0) {
    const float u0 = g_u[b * SEQ + ri] + bias[0];
    __half* erow = g_E + ((size_t)b * SEQ + ri) * 1024 + j0 + chalf;
    float rsum = 0.f;
#pragma unroll
    for (int q = 0; q < 16; ++q) {
      float4 s4 = *(const float4*)(srow + q * 4);
      const int col = j0 + chalf + q * 4;
      float e0 = __expf(tanhf(s4.x + u0 + g_v[b * SEQ + col]));
      float e1 = __expf(tanhf(s4.y + u0 + g_v[b * SEQ + col + 1]));
      float e2 = __expf(tanhf(s4.z + u0 + g_v[b * SEQ + col + 2]));
      float e3 = __expf(tanhf(s4.w + u0 + g_v[b * SEQ + col + 3]));
      rsum += (e0 + e1) + (e2 + e3);
      *(__half2*)(erow + q * 4)     = __floats2half2_rn(e0, e1);
      *(__half2*)(erow + q * 4 + 2) = __floats2half2_rn(e2, e3);
    }
    rsum += __shfl_xor_sync(0xffffffff, rsum, 1);
    if ((tid & 1) == 0)
      g_rpart[(size_t)blockIdx.x * (NB * SEQ) + b * SEQ + ri] = rsum;
  } else {
    const float iv = ((MODE == 1) ? g_rinv : g_cinv)[b * SEQ + ri];
    float4* orow = (float4*)(out + ((size_t)b * SEQ + ri) * 2048 + 1024 + j0 + chalf);
#pragma unroll
    for (int q = 0; q < 16; ++q) {
      float4 s4 = *(const float4*)(srow + q * 4);
      orow[q] = make_float4(s4.x * iv, s4.y * iv, s4.z * iv, s4.w * iv);
    }
  }
}

__global__ __launch_bounds__(256) void score_kernel(const float* __restrict__ bias,
                                                    float* __restrict__ out) {
  extern __shared__ char smem[];
  gemm_body<0>(blockIdx.z, bias, out, smem);
}

// merged av kernel: z<16 -> MODE1 (lhs attn), z>=16 -> MODE2 (rhs attn)
__global__ __launch_bounds__(256) void av_kernel(const float* __restrict__ bias,
                                                 float* __restrict__ out) {
  extern __shared__ char smem[];
  if (blockIdx.z < NB) gemm_body<1>(blockIdx.z, bias, out, smem);
  else                 gemm_body<2>(blockIdx.z - NB, bias, out + OFF2, smem);
}

// ---------------------------------------------------------------------------
// colsum(E) partials over 128-row chunks (coalesced in r)
// ---------------------------------------------------------------------------
__global__ void colsum_part() {
  const int b = blockIdx.z, chunk = blockIdx.y;
  const int r = blockIdx.x * 256 + threadIdx.x;
  const __half* e = g_E + (size_t)b * SEQ * SEQ + (size_t)chunk * 128 * SEQ + r;
  float s = 0.f;
#pragma unroll 8
  for (int l = 0; l < 128; l++) s += __half2float(e[(size_t)l * SEQ]);
  g_cpart[(b * 8 + chunk) * SEQ + r] = s;
}

// ---------------------------------------------------------------------------
// finalize: rinv from 8 row partials, cinv from 8 col partials
// ---------------------------------------------------------------------------
__global__ void finalize_kernel() {
  const int idx = blockIdx.x * 256 + threadIdx.x;
  const int b = idx >> 10;
  float sr = 0.f, sc = 0.f;
#pragma unroll
  for (int j = 0; j < 8; j++) sr += g_rpart[(size_t)j * (NB * SEQ) + idx];
#pragma unroll
  for (int c = 0; c < 8; c++) sc += g_cpart[(b * 8 + c) * SEQ + (idx & 1023)];
  g_rinv[idx] = 1.0f / sr;
  g_cinv[idx] = 1.0f / sc;
}

// ---------------------------------------------------------------------------
extern "C" void kernel_launch(void* const* d_in, const int* in_sizes, int n_in,
                              void* d_out, int out_size) {
  const float* lhs = (const float*)d_in[0];
  const float* rhs = (const float*)d_in[1];
  const float* w   = (const float*)d_in[2];
  const float* bp  = (const float*)d_in[3];
  float* out = (float*)d_out;

  cudaFuncSetAttribute(score_kernel, cudaFuncAttributeMaxDynamicSharedMemorySize, GSMEM);
  cudaFuncSetAttribute(av_kernel,    cudaFuncAttributeMaxDynamicSharedMemorySize, GSMEM);

  fuse_kernel<<<NB * SEQ, 256>>>((const float4*)lhs, (const float4*)rhs,
                                 (const float4*)w, (float4*)out);

  score_kernel<<<dim3(8, 8, NB), 256, GSMEM>>>(bp, out);   // -> g_E + rpart
  colsum_part<<<dim3(4, 8, NB), 256>>>();
  finalize_kernel<<<NB * SEQ / 256, 256>>>();              // rinv + cinv

  av_kernel<<<dim3(8, 8, 2 * NB), 256, GSMEM>>>(bp, out);  // both attn outputs
}